// round 1
// baseline (speedup 1.0000x reference)
#include <cuda_runtime.h>
#include <math.h>

#define NN 100000
#define EE 1200000
#define CH 128

// ---------------- device scratch (no allocations allowed) ----------------
__device__ int g_degP[NN], g_degN[NN], g_curP[NN], g_curN[NN];
__device__ int g_rpP[NN + 1], g_rpN[NN + 1];
__device__ int g_colP[EE], g_colN[EE];
__device__ float g_U[(size_t)NN * CH];
__device__ float g_V[(size_t)NN * CH];
__device__ float g_R[(size_t)NN * CH];
__device__ float g_Z[(size_t)NN * CH];
__device__ int g_is64;

// ---------------- dtype detection (int64 vs int32 edge indices) ----------
// If int64: every odd 32-bit word (high word) of the first 2048 words is 0.
// If int32: those words are random node ids -> virtually never all zero.
__global__ void detect_kernel(const unsigned int* __restrict__ p) {
    __shared__ int bad;
    if (threadIdx.x == 0) bad = 0;
    __syncthreads();
    if (p[threadIdx.x * 2 + 1] != 0u) bad = 1;
    __syncthreads();
    if (threadIdx.x == 0) g_is64 = (bad == 0) ? 1 : 0;
}

// ---------------- CSR build ----------------------------------------------
__global__ void hist_kernel(const void* __restrict__ ed, int E, int* __restrict__ deg) {
    int e = blockIdx.x * blockDim.x + threadIdx.x;
    if (e >= E) return;
    int d;
    if (g_is64) d = (int)((const long long*)ed)[(size_t)E + e];
    else        d = ((const int*)ed)[(size_t)E + e];
    atomicAdd(&deg[d], 1);
}

__global__ void fill_kernel(const void* __restrict__ ed, int E,
                            const int* __restrict__ rp, int* __restrict__ cur,
                            int* __restrict__ col) {
    int e = blockIdx.x * blockDim.x + threadIdx.x;
    if (e >= E) return;
    int s, d;
    if (g_is64) {
        s = (int)((const long long*)ed)[e];
        d = (int)((const long long*)ed)[(size_t)E + e];
    } else {
        s = ((const int*)ed)[e];
        d = ((const int*)ed)[(size_t)E + e];
    }
    int slot = rp[d] + atomicAdd(&cur[d], 1);
    col[slot] = s;
}

// single-block exclusive scan over n (~100K) ints
__global__ void exscan_kernel(const int* __restrict__ deg, int* __restrict__ rp, int n) {
    __shared__ int wt[32];
    __shared__ int s_carry;
    int t = threadIdx.x;
    if (t == 0) s_carry = 0;
    __syncthreads();
    for (int base = 0; base < n; base += 1024) {
        int v = (base + t < n) ? deg[base + t] : 0;
        int x = v;
        #pragma unroll
        for (int off = 1; off < 32; off <<= 1) {
            int y = __shfl_up_sync(0xffffffffu, x, off);
            if ((t & 31) >= off) x += y;
        }
        if ((t & 31) == 31) wt[t >> 5] = x;
        __syncthreads();
        if (t < 32) {
            int w = wt[t];
            #pragma unroll
            for (int off = 1; off < 32; off <<= 1) {
                int y = __shfl_up_sync(0xffffffffu, w, off);
                if (t >= off) w += y;
            }
            wt[t] = w;
        }
        __syncthreads();
        int incl = x + ((t >> 5) ? wt[(t >> 5) - 1] : 0);
        int carry = s_carry;
        if (base + t < n) rp[base + t] = carry + incl - v;
        __syncthreads();
        if (t == 1023) s_carry = carry + incl;
        __syncthreads();
    }
    if (t == 0) rp[n] = s_carry;
}

// ---------------- GEMM: (n x K) @ (K x 64) -> strided 64-col group --------
// All inputs/outputs have row stride CH=128. Weights are K x 64 row-major
// (exactly how the jax weights are laid out, so we point straight into them).
struct GemmGroup { const float* A; const float* W; const float* bias; float* O; };
struct GemmParams { GemmGroup g[6]; int K; int nrows; };

__global__ void __launch_bounds__(256) gemm_kernel(GemmParams p) {
    __shared__ float As[64][128];   // transposed: As[k][m]
    __shared__ float Bs[64][64];
    GemmGroup gg = p.g[blockIdx.y];
    int row0 = blockIdx.x * 128;
    int t = threadIdx.x;
    int tc = t & 15;        // 16 col groups x 4 cols
    int tr = t >> 4;        // 16 row groups x 8 rows
    float acc[8][4];
    #pragma unroll
    for (int r = 0; r < 8; r++)
        #pragma unroll
        for (int c = 0; c < 4; c++) acc[r][c] = 0.f;

    for (int kb = 0; kb < p.K; kb += 64) {
        // A chunk: 128 rows x 64 k, transposed into smem
        {
            int m = t >> 1;
            int half = t & 1;
            int r = row0 + m;
            const float* ap = gg.A + (size_t)r * CH + kb + half * 32;
            #pragma unroll
            for (int j = 0; j < 8; j++) {
                float4 v = make_float4(0.f, 0.f, 0.f, 0.f);
                if (r < p.nrows) v = *(const float4*)(ap + j * 4);
                int k = half * 32 + j * 4;
                As[k + 0][m] = v.x; As[k + 1][m] = v.y;
                As[k + 2][m] = v.z; As[k + 3][m] = v.w;
            }
        }
        // B chunk: 64 k x 64 cols
        {
            int col = (t & 15) * 4;
            int kr = t >> 4;
            #pragma unroll
            for (int j = 0; j < 4; j++) {
                int k = kr + j * 16;
                *(float4*)&Bs[k][col] = *(const float4*)(gg.W + (size_t)(kb + k) * 64 + col);
            }
        }
        __syncthreads();
        #pragma unroll 16
        for (int kk = 0; kk < 64; kk++) {
            float4 a0 = *(const float4*)&As[kk][tr * 8];
            float4 a1 = *(const float4*)&As[kk][tr * 8 + 4];
            float4 b  = *(const float4*)&Bs[kk][tc * 4];
            float av[8] = {a0.x, a0.y, a0.z, a0.w, a1.x, a1.y, a1.z, a1.w};
            float bv[4] = {b.x, b.y, b.z, b.w};
            #pragma unroll
            for (int r = 0; r < 8; r++)
                #pragma unroll
                for (int c = 0; c < 4; c++)
                    acc[r][c] = fmaf(av[r], bv[c], acc[r][c]);
        }
        __syncthreads();
    }
    float bb[4] = {0.f, 0.f, 0.f, 0.f};
    if (gg.bias) {
        bb[0] = gg.bias[tc * 4 + 0]; bb[1] = gg.bias[tc * 4 + 1];
        bb[2] = gg.bias[tc * 4 + 2]; bb[3] = gg.bias[tc * 4 + 3];
    }
    #pragma unroll
    for (int r = 0; r < 8; r++) {
        int row = row0 + tr * 8 + r;
        if (row < p.nrows) {
            float4 o = make_float4(acc[r][0] + bb[0], acc[r][1] + bb[1],
                                   acc[r][2] + bb[2], acc[r][3] + bb[3]);
            *(float4*)(gg.O + (size_t)row * CH + tc * 4) = o;
        }
    }
}

// ---------------- layer-0 aggregation: 1 warp per node --------------------
// z[:, :64] = tanh(R[:, :64] + meanpos(U[:, :64]))
// z[:, 64:] = tanh(R[:, 64:] + meanneg(U[:, 64:]))
__global__ void agg0_kernel(int n, float* __restrict__ Z) {
    int w = (blockIdx.x * blockDim.x + threadIdx.x) >> 5;
    if (w >= n) return;
    int lane = threadIdx.x & 31;
    int c = lane * 2;
    const float* U = g_U;

    float sx0 = 0.f, sy0 = 0.f, sx1 = 0.f, sy1 = 0.f;
    int b = g_rpP[w], e = g_rpP[w + 1];
    float invp = 1.0f / (float)((e - b) > 0 ? (e - b) : 1);
    int i = b;
    for (; i + 2 <= e; i += 2) {
        int ia = g_colP[i], ib = g_colP[i + 1];
        float2 ga = *(const float2*)(U + (size_t)ia * CH + c);
        float2 gb = *(const float2*)(U + (size_t)ib * CH + c);
        sx0 += ga.x; sy0 += ga.y; sx1 += gb.x; sy1 += gb.y;
    }
    if (i < e) {
        float2 ga = *(const float2*)(U + (size_t)g_colP[i] * CH + c);
        sx0 += ga.x; sy0 += ga.y;
    }
    float sumpx = sx0 + sx1, sumpy = sy0 + sy1;

    float tx0 = 0.f, ty0 = 0.f, tx1 = 0.f, ty1 = 0.f;
    b = g_rpN[w]; e = g_rpN[w + 1];
    float invn = 1.0f / (float)((e - b) > 0 ? (e - b) : 1);
    i = b;
    for (; i + 2 <= e; i += 2) {
        int ia = g_colN[i], ib = g_colN[i + 1];
        float2 ga = *(const float2*)(U + (size_t)ia * CH + 64 + c);
        float2 gb = *(const float2*)(U + (size_t)ib * CH + 64 + c);
        tx0 += ga.x; ty0 += ga.y; tx1 += gb.x; ty1 += gb.y;
    }
    if (i < e) {
        float2 ga = *(const float2*)(U + (size_t)g_colN[i] * CH + 64 + c);
        tx0 += ga.x; ty0 += ga.y;
    }
    float sumnx = tx0 + tx1, sumny = ty0 + ty1;

    float2 r0 = *(const float2*)(g_R + (size_t)w * CH + c);
    float2 r1 = *(const float2*)(g_R + (size_t)w * CH + 64 + c);
    float2 zp, zn;
    zp.x = tanhf(r0.x + invp * sumpx);
    zp.y = tanhf(r0.y + invp * sumpy);
    zn.x = tanhf(r1.x + invn * sumnx);
    zn.y = tanhf(r1.y + invn * sumny);
    *(float2*)(Z + (size_t)w * CH + c) = zp;
    *(float2*)(Z + (size_t)w * CH + 64 + c) = zn;
}

// ---------------- loop-layer aggregation: 1 warp per node -----------------
// out = tanh(R + invp * sum_pos U[src, 0:128] + invn * sum_neg V[src, 0:128])
__global__ void aggl_kernel(int n, float* __restrict__ out) {
    int w = (blockIdx.x * blockDim.x + threadIdx.x) >> 5;
    if (w >= n) return;
    int lane = threadIdx.x & 31;
    int c = lane * 4;

    float4 s0 = make_float4(0.f, 0.f, 0.f, 0.f);
    float4 s1 = make_float4(0.f, 0.f, 0.f, 0.f);
    int b = g_rpP[w], e = g_rpP[w + 1];
    float invp = 1.0f / (float)((e - b) > 0 ? (e - b) : 1);
    int i = b;
    for (; i + 2 <= e; i += 2) {
        int ia = g_colP[i], ib = g_colP[i + 1];
        float4 ga = *(const float4*)(g_U + (size_t)ia * CH + c);
        float4 gb = *(const float4*)(g_U + (size_t)ib * CH + c);
        s0.x += ga.x; s0.y += ga.y; s0.z += ga.z; s0.w += ga.w;
        s1.x += gb.x; s1.y += gb.y; s1.z += gb.z; s1.w += gb.w;
    }
    if (i < e) {
        float4 ga = *(const float4*)(g_U + (size_t)g_colP[i] * CH + c);
        s0.x += ga.x; s0.y += ga.y; s0.z += ga.z; s0.w += ga.w;
    }

    float4 t0 = make_float4(0.f, 0.f, 0.f, 0.f);
    float4 t1 = make_float4(0.f, 0.f, 0.f, 0.f);
    b = g_rpN[w]; e = g_rpN[w + 1];
    float invn = 1.0f / (float)((e - b) > 0 ? (e - b) : 1);
    i = b;
    for (; i + 2 <= e; i += 2) {
        int ia = g_colN[i], ib = g_colN[i + 1];
        float4 ga = *(const float4*)(g_V + (size_t)ia * CH + c);
        float4 gb = *(const float4*)(g_V + (size_t)ib * CH + c);
        t0.x += ga.x; t0.y += ga.y; t0.z += ga.z; t0.w += ga.w;
        t1.x += gb.x; t1.y += gb.y; t1.z += gb.z; t1.w += gb.w;
    }
    if (i < e) {
        float4 ga = *(const float4*)(g_V + (size_t)g_colN[i] * CH + c);
        t0.x += ga.x; t0.y += ga.y; t0.z += ga.z; t0.w += ga.w;
    }

    float4 r = *(const float4*)(g_R + (size_t)w * CH + c);
    float4 o;
    o.x = tanhf(r.x + invp * (s0.x + s1.x) + invn * (t0.x + t1.x));
    o.y = tanhf(r.y + invp * (s0.y + s1.y) + invn * (t0.y + t1.y));
    o.z = tanhf(r.z + invp * (s0.z + s1.z) + invn * (t0.z + t1.z));
    o.w = tanhf(r.w + invp * (s0.w + s1.w) + invn * (t0.w + t1.w));
    *(float4*)(out + (size_t)w * CH + c) = o;
}

// ---------------- host driver --------------------------------------------
extern "C" void kernel_launch(void* const* d_in, const int* in_sizes, int n_in,
                              void* d_out, int out_size) {
    const float* x      = (const float*)d_in[0];
    const void*  pe     = d_in[1];
    const void*  nedge  = d_in[2];
    const float* Wp_l   = (const float*)d_in[3];
    const float* Wp_r   = (const float*)d_in[4];
    const float* bp     = (const float*)d_in[5];
    const float* Wn_l   = (const float*)d_in[6];
    const float* Wn_r   = (const float*)d_in[7];
    const float* bn     = (const float*)d_in[8];
    const float* Wl_pos = (const float*)d_in[9];
    const float* Wr_pos = (const float*)d_in[10];
    const float* b_pos  = (const float*)d_in[11];
    const float* Wl_neg = (const float*)d_in[12];
    const float* Wr_neg = (const float*)d_in[13];
    const float* b_neg  = (const float*)d_in[14];

    int n = in_sizes[0] / CH;
    int E = in_sizes[1] / 2;
    if (n > NN) n = NN;
    if (E > EE) E = EE;

    void *pU, *pV, *pR, *pZ, *pDegP, *pDegN, *pCurP, *pCurN, *pRpP, *pRpN, *pColP, *pColN;
    cudaGetSymbolAddress(&pU, g_U);
    cudaGetSymbolAddress(&pV, g_V);
    cudaGetSymbolAddress(&pR, g_R);
    cudaGetSymbolAddress(&pZ, g_Z);
    cudaGetSymbolAddress(&pDegP, g_degP);
    cudaGetSymbolAddress(&pDegN, g_degN);
    cudaGetSymbolAddress(&pCurP, g_curP);
    cudaGetSymbolAddress(&pCurN, g_curN);
    cudaGetSymbolAddress(&pRpP, g_rpP);
    cudaGetSymbolAddress(&pRpN, g_rpN);
    cudaGetSymbolAddress(&pColP, g_colP);
    cudaGetSymbolAddress(&pColN, g_colN);

    cudaMemsetAsync(pDegP, 0, n * sizeof(int));
    cudaMemsetAsync(pDegN, 0, n * sizeof(int));
    cudaMemsetAsync(pCurP, 0, n * sizeof(int));
    cudaMemsetAsync(pCurN, 0, n * sizeof(int));

    detect_kernel<<<1, 1024>>>((const unsigned int*)pe);

    int eg = (E + 255) / 256;
    hist_kernel<<<eg, 256>>>(pe, E, (int*)pDegP);
    hist_kernel<<<eg, 256>>>(nedge, E, (int*)pDegN);
    exscan_kernel<<<1, 1024>>>((const int*)pDegP, (int*)pRpP, n);
    exscan_kernel<<<1, 1024>>>((const int*)pDegN, (int*)pRpN, n);
    fill_kernel<<<eg, 256>>>(pe, E, (const int*)pRpP, (int*)pCurP, (int*)pColP);
    fill_kernel<<<eg, 256>>>(nedge, E, (const int*)pRpN, (int*)pCurN, (int*)pColN);

    int mg = (n + 127) / 128;
    int wg = (n * 32 + 255) / 256;

    // layer 0: U[:, :64] = x@Wp_l, U[:, 64:] = x@Wn_l,
    //          R[:, :64] = x@Wp_r + bp, R[:, 64:] = x@Wn_r + bn
    GemmParams p0;
    p0.K = CH; p0.nrows = n;
    p0.g[0] = GemmGroup{ x, Wp_l, nullptr, (float*)pU };
    p0.g[1] = GemmGroup{ x, Wn_l, nullptr, (float*)pU + 64 };
    p0.g[2] = GemmGroup{ x, Wp_r, bp,      (float*)pR };
    p0.g[3] = GemmGroup{ x, Wn_r, bn,      (float*)pR + 64 };
    p0.g[4] = p0.g[0]; p0.g[5] = p0.g[0];
    gemm_kernel<<<dim3(mg, 4), 256>>>(p0);
    agg0_kernel<<<wg, 256>>>(n, (float*)pZ);

    // loop layers: push GEMMs through the (linear) aggregations
    for (int l = 0; l < 2; l++) {
        const float* zp = (const float*)pZ;       // x_p = z[:, :64]
        const float* zn = (const float*)pZ + 64;  // x_n = z[:, 64:]
        GemmParams pl;
        pl.K = 64; pl.nrows = n;
        // U (gathered over pos edges): [x_p@A1 | x_n@B1]
        pl.g[0] = GemmGroup{ zp, Wl_pos + l * 8192,        nullptr,        (float*)pU };
        pl.g[1] = GemmGroup{ zn, Wl_neg + l * 8192,        nullptr,        (float*)pU + 64 };
        // V (gathered over neg edges): [x_n@A2 | x_p@B2]
        pl.g[2] = GemmGroup{ zn, Wl_pos + l * 8192 + 4096, nullptr,        (float*)pV };
        pl.g[3] = GemmGroup{ zp, Wl_neg + l * 8192 + 4096, nullptr,        (float*)pV + 64 };
        // R (residual): [x_p@Wr_pos + b_pos | x_n@Wr_neg + b_neg]
        pl.g[4] = GemmGroup{ zp, Wr_pos + l * 4096,        b_pos + l * 64, (float*)pR };
        pl.g[5] = GemmGroup{ zn, Wr_neg + l * 4096,        b_neg + l * 64, (float*)pR + 64 };
        gemm_kernel<<<dim3(mg, 6), 256>>>(pl);

        float* outp = (l == 1) ? (float*)d_out : (float*)pZ;
        aggl_kernel<<<wg, 256>>>(n, outp);
    }
}

// round 2
// speedup vs baseline: 1.1085x; 1.1085x over previous
#include <cuda_runtime.h>
#include <math.h>

#define NN 100000
#define EE 1200000
#define CH 128
#define SCHUNK 512
#define MAXCHUNK 200   // ceil(100000/512)=196

// ---------------- device scratch (no allocations allowed) ----------------
__device__ int g_degP[NN], g_degN[NN], g_curP[NN], g_curN[NN];
__device__ int g_rpP[NN + 1], g_rpN[NN + 1];
__device__ int g_colP[EE], g_colN[EE];
__device__ int g_partP[MAXCHUNK], g_partN[MAXCHUNK];
__device__ float g_U[(size_t)NN * CH];
__device__ float g_V[(size_t)NN * CH];
__device__ float g_R[(size_t)NN * CH];
__device__ float g_Z[(size_t)NN * CH];
__device__ int g_is64;

// ---------------- dtype detection (int64 vs int32 edge indices) ----------
__global__ void detect_kernel(const unsigned int* __restrict__ p) {
    __shared__ int bad;
    if (threadIdx.x == 0) bad = 0;
    __syncthreads();
    if (p[threadIdx.x * 2 + 1] != 0u) bad = 1;
    __syncthreads();
    if (threadIdx.x == 0) g_is64 = (bad == 0) ? 1 : 0;
}

// ---------------- CSR build ----------------------------------------------
// histogram for both edge sets in one launch (grid.y selects set)
__global__ void hist2_kernel(const void* __restrict__ e1, const void* __restrict__ e2,
                             int E) {
    int e = blockIdx.x * blockDim.x + threadIdx.x;
    if (e >= E) return;
    const void* ed = blockIdx.y ? e2 : e1;
    int* deg = blockIdx.y ? g_degN : g_degP;
    int d;
    if (g_is64) d = (int)((const long long*)ed)[(size_t)E + e];
    else        d = ((const int*)ed)[(size_t)E + e];
    atomicAdd(&deg[d], 1);
}

// scan phase 1: per-chunk reduction (512 elems / block), both arrays
__global__ void __launch_bounds__(SCHUNK) scan_part_kernel(int n) {
    const int* deg = blockIdx.y ? g_degN : g_degP;
    int* part = blockIdx.y ? g_partN : g_partP;
    int t = threadIdx.x;
    int i = blockIdx.x * SCHUNK + t;
    int v = (i < n) ? deg[i] : 0;
    #pragma unroll
    for (int off = 16; off > 0; off >>= 1)
        v += __shfl_down_sync(0xffffffffu, v, off);
    __shared__ int ws[16];
    if ((t & 31) == 0) ws[t >> 5] = v;
    __syncthreads();
    if (t < 16) {
        int r = ws[t];
        #pragma unroll
        for (int off = 8; off > 0; off >>= 1)
            r += __shfl_down_sync(0x0000ffffu, r, off);
        if (t == 0) part[blockIdx.x] = r;
    }
}

// scan phase 2: exclusive scan of chunk partials (one block, both arrays)
__global__ void __launch_bounds__(256) scan_mid_kernel(int nchunk) {
    __shared__ int wt[8];
    int t = threadIdx.x;
    for (int a = 0; a < 2; a++) {
        int* part = a ? g_partN : g_partP;
        int v = (t < nchunk) ? part[t] : 0;
        int x = v;
        #pragma unroll
        for (int off = 1; off < 32; off <<= 1) {
            int y = __shfl_up_sync(0xffffffffu, x, off);
            if ((t & 31) >= off) x += y;
        }
        if ((t & 31) == 31) wt[t >> 5] = x;
        __syncthreads();
        if (t < 8) {
            int w = wt[t];
            #pragma unroll
            for (int off = 1; off < 8; off <<= 1) {
                int y = __shfl_up_sync(0x000000ffu, w, off);
                if (t >= off) w += y;
            }
            wt[t] = w;
        }
        __syncthreads();
        int incl = x + ((t >> 5) ? wt[(t >> 5) - 1] : 0);
        if (t < nchunk) part[t] = incl - v;   // exclusive
        __syncthreads();
    }
}

// scan phase 3: chunk-local exclusive scan + chunk offset -> rp and cur
__global__ void __launch_bounds__(SCHUNK) scan_final_kernel(int n, int E) {
    const int* deg = blockIdx.y ? g_degN : g_degP;
    const int* part = blockIdx.y ? g_partN : g_partP;
    int* rp = blockIdx.y ? g_rpN : g_rpP;
    int* cur = blockIdx.y ? g_curN : g_curP;
    int t = threadIdx.x;
    int i = blockIdx.x * SCHUNK + t;
    int v = (i < n) ? deg[i] : 0;
    int x = v;
    #pragma unroll
    for (int off = 1; off < 32; off <<= 1) {
        int y = __shfl_up_sync(0xffffffffu, x, off);
        if ((t & 31) >= off) x += y;
    }
    __shared__ int ws[16];
    if ((t & 31) == 31) ws[t >> 5] = x;
    __syncthreads();
    if (t < 16) {
        int w = ws[t];
        #pragma unroll
        for (int off = 1; off < 16; off <<= 1) {
            int y = __shfl_up_sync(0x0000ffffu, w, off);
            if (t >= off) w += y;
        }
        ws[t] = w;
    }
    __syncthreads();
    int incl = x + ((t >> 5) ? ws[(t >> 5) - 1] : 0);
    int excl = incl - v + part[blockIdx.x];
    if (i < n) { rp[i] = excl; cur[i] = excl; }
    if (blockIdx.x == 0 && t == 0) rp[n] = E;
}

// fill for both edge sets (cur pre-seeded with rp, so no rp read needed)
__global__ void fill2_kernel(const void* __restrict__ e1, const void* __restrict__ e2,
                             int E) {
    int e = blockIdx.x * blockDim.x + threadIdx.x;
    if (e >= E) return;
    const void* ed = blockIdx.y ? e2 : e1;
    int* cur = blockIdx.y ? g_curN : g_curP;
    int* col = blockIdx.y ? g_colN : g_colP;
    int s, d;
    if (g_is64) {
        s = (int)((const long long*)ed)[e];
        d = (int)((const long long*)ed)[(size_t)E + e];
    } else {
        s = ((const int*)ed)[e];
        d = ((const int*)ed)[(size_t)E + e];
    }
    int slot = atomicAdd(&cur[d], 1);
    col[slot] = s;
}

// ---------------- GEMM: (n x K) @ (K x 64) -> strided 64-col group --------
struct GemmGroup { const float* A; const float* W; const float* bias; float* O; };
struct GemmParams { GemmGroup g[6]; int K; int nrows; };

__global__ void __launch_bounds__(256) gemm_kernel(GemmParams p) {
    __shared__ float As[64][128];   // transposed: As[k][m]
    __shared__ float Bs[64][64];
    GemmGroup gg = p.g[blockIdx.y];
    int row0 = blockIdx.x * 128;
    int t = threadIdx.x;
    int tc = t & 15;
    int tr = t >> 4;
    float acc[8][4];
    #pragma unroll
    for (int r = 0; r < 8; r++)
        #pragma unroll
        for (int c = 0; c < 4; c++) acc[r][c] = 0.f;

    for (int kb = 0; kb < p.K; kb += 64) {
        {
            int m = t >> 1;
            int half = t & 1;
            int r = row0 + m;
            const float* ap = gg.A + (size_t)r * CH + kb + half * 32;
            #pragma unroll
            for (int j = 0; j < 8; j++) {
                float4 v = make_float4(0.f, 0.f, 0.f, 0.f);
                if (r < p.nrows) v = *(const float4*)(ap + j * 4);
                int k = half * 32 + j * 4;
                As[k + 0][m] = v.x; As[k + 1][m] = v.y;
                As[k + 2][m] = v.z; As[k + 3][m] = v.w;
            }
        }
        {
            int col = (t & 15) * 4;
            int kr = t >> 4;
            #pragma unroll
            for (int j = 0; j < 4; j++) {
                int k = kr + j * 16;
                *(float4*)&Bs[k][col] = *(const float4*)(gg.W + (size_t)(kb + k) * 64 + col);
            }
        }
        __syncthreads();
        #pragma unroll 16
        for (int kk = 0; kk < 64; kk++) {
            float4 a0 = *(const float4*)&As[kk][tr * 8];
            float4 a1 = *(const float4*)&As[kk][tr * 8 + 4];
            float4 b  = *(const float4*)&Bs[kk][tc * 4];
            float av[8] = {a0.x, a0.y, a0.z, a0.w, a1.x, a1.y, a1.z, a1.w};
            float bv[4] = {b.x, b.y, b.z, b.w};
            #pragma unroll
            for (int r = 0; r < 8; r++)
                #pragma unroll
                for (int c = 0; c < 4; c++)
                    acc[r][c] = fmaf(av[r], bv[c], acc[r][c]);
        }
        __syncthreads();
    }
    float bb[4] = {0.f, 0.f, 0.f, 0.f};
    if (gg.bias) {
        bb[0] = gg.bias[tc * 4 + 0]; bb[1] = gg.bias[tc * 4 + 1];
        bb[2] = gg.bias[tc * 4 + 2]; bb[3] = gg.bias[tc * 4 + 3];
    }
    #pragma unroll
    for (int r = 0; r < 8; r++) {
        int row = row0 + tr * 8 + r;
        if (row < p.nrows) {
            float4 o = make_float4(acc[r][0] + bb[0], acc[r][1] + bb[1],
                                   acc[r][2] + bb[2], acc[r][3] + bb[3]);
            *(float4*)(gg.O + (size_t)row * CH + tc * 4) = o;
        }
    }
}

// ---------------- layer-0 aggregation: 1 warp per node --------------------
__global__ void agg0_kernel(int n, float* __restrict__ Z) {
    int w = (blockIdx.x * blockDim.x + threadIdx.x) >> 5;
    if (w >= n) return;
    int lane = threadIdx.x & 31;
    int c = lane * 2;
    const float* U = g_U;

    float sx0 = 0.f, sy0 = 0.f, sx1 = 0.f, sy1 = 0.f;
    int b = g_rpP[w], e = g_rpP[w + 1];
    float invp = 1.0f / (float)((e - b) > 0 ? (e - b) : 1);
    int i = b;
    for (; i + 2 <= e; i += 2) {
        int ia = g_colP[i], ib = g_colP[i + 1];
        float2 ga = *(const float2*)(U + (size_t)ia * CH + c);
        float2 gb = *(const float2*)(U + (size_t)ib * CH + c);
        sx0 += ga.x; sy0 += ga.y; sx1 += gb.x; sy1 += gb.y;
    }
    if (i < e) {
        float2 ga = *(const float2*)(U + (size_t)g_colP[i] * CH + c);
        sx0 += ga.x; sy0 += ga.y;
    }
    float sumpx = sx0 + sx1, sumpy = sy0 + sy1;

    float tx0 = 0.f, ty0 = 0.f, tx1 = 0.f, ty1 = 0.f;
    b = g_rpN[w]; e = g_rpN[w + 1];
    float invn = 1.0f / (float)((e - b) > 0 ? (e - b) : 1);
    i = b;
    for (; i + 2 <= e; i += 2) {
        int ia = g_colN[i], ib = g_colN[i + 1];
        float2 ga = *(const float2*)(U + (size_t)ia * CH + 64 + c);
        float2 gb = *(const float2*)(U + (size_t)ib * CH + 64 + c);
        tx0 += ga.x; ty0 += ga.y; tx1 += gb.x; ty1 += gb.y;
    }
    if (i < e) {
        float2 ga = *(const float2*)(U + (size_t)g_colN[i] * CH + 64 + c);
        tx0 += ga.x; ty0 += ga.y;
    }
    float sumnx = tx0 + tx1, sumny = ty0 + ty1;

    float2 r0 = *(const float2*)(g_R + (size_t)w * CH + c);
    float2 r1 = *(const float2*)(g_R + (size_t)w * CH + 64 + c);
    float2 zp, zn;
    zp.x = tanhf(r0.x + invp * sumpx);
    zp.y = tanhf(r0.y + invp * sumpy);
    zn.x = tanhf(r1.x + invn * sumnx);
    zn.y = tanhf(r1.y + invn * sumny);
    *(float2*)(Z + (size_t)w * CH + c) = zp;
    *(float2*)(Z + (size_t)w * CH + 64 + c) = zn;
}

// ---------------- loop-layer aggregation: 1 warp per node, unroll 4 -------
__global__ void aggl_kernel(int n, float* __restrict__ out) {
    int w = (blockIdx.x * blockDim.x + threadIdx.x) >> 5;
    if (w >= n) return;
    int lane = threadIdx.x & 31;
    int c = lane * 4;

    float4 s0 = make_float4(0.f, 0.f, 0.f, 0.f);
    float4 s1 = make_float4(0.f, 0.f, 0.f, 0.f);
    float4 s2 = make_float4(0.f, 0.f, 0.f, 0.f);
    float4 s3 = make_float4(0.f, 0.f, 0.f, 0.f);
    int b = g_rpP[w], e = g_rpP[w + 1];
    float invp = 1.0f / (float)((e - b) > 0 ? (e - b) : 1);
    int i = b;
    for (; i + 4 <= e; i += 4) {
        int ia = g_colP[i], ib = g_colP[i + 1], ic = g_colP[i + 2], id = g_colP[i + 3];
        float4 ga = *(const float4*)(g_U + (size_t)ia * CH + c);
        float4 gb = *(const float4*)(g_U + (size_t)ib * CH + c);
        float4 gc = *(const float4*)(g_U + (size_t)ic * CH + c);
        float4 gd = *(const float4*)(g_U + (size_t)id * CH + c);
        s0.x += ga.x; s0.y += ga.y; s0.z += ga.z; s0.w += ga.w;
        s1.x += gb.x; s1.y += gb.y; s1.z += gb.z; s1.w += gb.w;
        s2.x += gc.x; s2.y += gc.y; s2.z += gc.z; s2.w += gc.w;
        s3.x += gd.x; s3.y += gd.y; s3.z += gd.z; s3.w += gd.w;
    }
    for (; i < e; i++) {
        float4 ga = *(const float4*)(g_U + (size_t)g_colP[i] * CH + c);
        s0.x += ga.x; s0.y += ga.y; s0.z += ga.z; s0.w += ga.w;
    }

    float4 t0 = make_float4(0.f, 0.f, 0.f, 0.f);
    float4 t1 = make_float4(0.f, 0.f, 0.f, 0.f);
    float4 t2 = make_float4(0.f, 0.f, 0.f, 0.f);
    float4 t3 = make_float4(0.f, 0.f, 0.f, 0.f);
    b = g_rpN[w]; e = g_rpN[w + 1];
    float invn = 1.0f / (float)((e - b) > 0 ? (e - b) : 1);
    i = b;
    for (; i + 4 <= e; i += 4) {
        int ia = g_colN[i], ib = g_colN[i + 1], ic = g_colN[i + 2], id = g_colN[i + 3];
        float4 ga = *(const float4*)(g_V + (size_t)ia * CH + c);
        float4 gb = *(const float4*)(g_V + (size_t)ib * CH + c);
        float4 gc = *(const float4*)(g_V + (size_t)ic * CH + c);
        float4 gd = *(const float4*)(g_V + (size_t)id * CH + c);
        t0.x += ga.x; t0.y += ga.y; t0.z += ga.z; t0.w += ga.w;
        t1.x += gb.x; t1.y += gb.y; t1.z += gb.z; t1.w += gb.w;
        t2.x += gc.x; t2.y += gc.y; t2.z += gc.z; t2.w += gc.w;
        t3.x += gd.x; t3.y += gd.y; t3.z += gd.z; t3.w += gd.w;
    }
    for (; i < e; i++) {
        float4 ga = *(const float4*)(g_V + (size_t)g_colN[i] * CH + c);
        t0.x += ga.x; t0.y += ga.y; t0.z += ga.z; t0.w += ga.w;
    }

    float4 r = *(const float4*)(g_R + (size_t)w * CH + c);
    float4 o;
    o.x = tanhf(r.x + invp * (s0.x + s1.x + s2.x + s3.x) + invn * (t0.x + t1.x + t2.x + t3.x));
    o.y = tanhf(r.y + invp * (s0.y + s1.y + s2.y + s3.y) + invn * (t0.y + t1.y + t2.y + t3.y));
    o.z = tanhf(r.z + invp * (s0.z + s1.z + s2.z + s3.z) + invn * (t0.z + t1.z + t2.z + t3.z));
    o.w = tanhf(r.w + invp * (s0.w + s1.w + s2.w + s3.w) + invn * (t0.w + t1.w + t2.w + t3.w));
    *(float4*)(out + (size_t)w * CH + c) = o;
}

// ---------------- host driver --------------------------------------------
extern "C" void kernel_launch(void* const* d_in, const int* in_sizes, int n_in,
                              void* d_out, int out_size) {
    const float* x      = (const float*)d_in[0];
    const void*  pe     = d_in[1];
    const void*  nedge  = d_in[2];
    const float* Wp_l   = (const float*)d_in[3];
    const float* Wp_r   = (const float*)d_in[4];
    const float* bp     = (const float*)d_in[5];
    const float* Wn_l   = (const float*)d_in[6];
    const float* Wn_r   = (const float*)d_in[7];
    const float* bn     = (const float*)d_in[8];
    const float* Wl_pos = (const float*)d_in[9];
    const float* Wr_pos = (const float*)d_in[10];
    const float* b_pos  = (const float*)d_in[11];
    const float* Wl_neg = (const float*)d_in[12];
    const float* Wr_neg = (const float*)d_in[13];
    const float* b_neg  = (const float*)d_in[14];

    int n = in_sizes[0] / CH;
    int E = in_sizes[1] / 2;
    if (n > NN) n = NN;
    if (E > EE) E = EE;

    void *pU, *pV, *pR, *pZ, *pDegP, *pDegN;
    cudaGetSymbolAddress(&pU, g_U);
    cudaGetSymbolAddress(&pV, g_V);
    cudaGetSymbolAddress(&pR, g_R);
    cudaGetSymbolAddress(&pZ, g_Z);
    cudaGetSymbolAddress(&pDegP, g_degP);
    cudaGetSymbolAddress(&pDegN, g_degN);

    cudaMemsetAsync(pDegP, 0, n * sizeof(int));
    cudaMemsetAsync(pDegN, 0, n * sizeof(int));

    detect_kernel<<<1, 1024>>>((const unsigned int*)pe);

    int eg = (E + 255) / 256;
    int nchunk = (n + SCHUNK - 1) / SCHUNK;
    hist2_kernel<<<dim3(eg, 2), 256>>>(pe, nedge, E);
    scan_part_kernel<<<dim3(nchunk, 2), SCHUNK>>>(n);
    scan_mid_kernel<<<1, 256>>>(nchunk);
    scan_final_kernel<<<dim3(nchunk, 2), SCHUNK>>>(n, E);
    fill2_kernel<<<dim3(eg, 2), 256>>>(pe, nedge, E);

    int mg = (n + 127) / 128;
    int wg = (n * 32 + 255) / 256;

    // layer 0
    GemmParams p0;
    p0.K = CH; p0.nrows = n;
    p0.g[0] = GemmGroup{ x, Wp_l, nullptr, (float*)pU };
    p0.g[1] = GemmGroup{ x, Wn_l, nullptr, (float*)pU + 64 };
    p0.g[2] = GemmGroup{ x, Wp_r, bp,      (float*)pR };
    p0.g[3] = GemmGroup{ x, Wn_r, bn,      (float*)pR + 64 };
    p0.g[4] = p0.g[0]; p0.g[5] = p0.g[0];
    gemm_kernel<<<dim3(mg, 4), 256>>>(p0);
    agg0_kernel<<<wg, 256>>>(n, (float*)pZ);

    // loop layers
    for (int l = 0; l < 2; l++) {
        const float* zp = (const float*)pZ;
        const float* zn = (const float*)pZ + 64;
        GemmParams pl;
        pl.K = 64; pl.nrows = n;
        pl.g[0] = GemmGroup{ zp, Wl_pos + l * 8192,        nullptr,        (float*)pU };
        pl.g[1] = GemmGroup{ zn, Wl_neg + l * 8192,        nullptr,        (float*)pU + 64 };
        pl.g[2] = GemmGroup{ zn, Wl_pos + l * 8192 + 4096, nullptr,        (float*)pV };
        pl.g[3] = GemmGroup{ zp, Wl_neg + l * 8192 + 4096, nullptr,        (float*)pV + 64 };
        pl.g[4] = GemmGroup{ zp, Wr_pos + l * 4096,        b_pos + l * 64, (float*)pR };
        pl.g[5] = GemmGroup{ zn, Wr_neg + l * 4096,        b_neg + l * 64, (float*)pR + 64 };
        gemm_kernel<<<dim3(mg, 6), 256>>>(pl);

        float* outp = (l == 1) ? (float*)d_out : (float*)pZ;
        aggl_kernel<<<wg, 256>>>(n, outp);
    }
}

// round 3
// speedup vs baseline: 1.3427x; 1.2114x over previous
#include <cuda_runtime.h>
#include <cuda_fp16.h>
#include <math.h>

#define NN 100000
#define EE 1200000
#define CH 128
#define SCHUNK 512
#define MAXCHUNK 200

// ---------------- device scratch ----------------
__device__ int g_degP[NN], g_degN[NN], g_curP[NN], g_curN[NN];
__device__ int g_rpP[NN + 1], g_rpN[NN + 1];
__device__ int g_colP[EE], g_colN[EE];
__device__ int g_partP[MAXCHUNK], g_partN[MAXCHUNK];
__device__ __half g_U[(size_t)NN * CH];
__device__ __half g_V[(size_t)NN * CH];
__device__ float g_R[(size_t)NN * CH];
__device__ float g_Z[(size_t)NN * CH];
__device__ int g_is64;

// ---------------- dtype detection ----------------
__global__ void detect_kernel(const unsigned int* __restrict__ p) {
    __shared__ int bad;
    if (threadIdx.x == 0) bad = 0;
    __syncthreads();
    if (p[threadIdx.x * 2 + 1] != 0u) bad = 1;
    __syncthreads();
    if (threadIdx.x == 0) g_is64 = (bad == 0) ? 1 : 0;
}

// ---------------- CSR build ----------------
__global__ void hist2_kernel(const void* __restrict__ e1, const void* __restrict__ e2,
                             int E) {
    int e = blockIdx.x * blockDim.x + threadIdx.x;
    if (e >= E) return;
    const void* ed = blockIdx.y ? e2 : e1;
    int* deg = blockIdx.y ? g_degN : g_degP;
    int d;
    if (g_is64) d = (int)((const long long*)ed)[(size_t)E + e];
    else        d = ((const int*)ed)[(size_t)E + e];
    atomicAdd(&deg[d], 1);
}

__global__ void __launch_bounds__(SCHUNK) scan_part_kernel(int n) {
    const int* deg = blockIdx.y ? g_degN : g_degP;
    int* part = blockIdx.y ? g_partN : g_partP;
    int t = threadIdx.x;
    int i = blockIdx.x * SCHUNK + t;
    int v = (i < n) ? deg[i] : 0;
    #pragma unroll
    for (int off = 16; off > 0; off >>= 1)
        v += __shfl_down_sync(0xffffffffu, v, off);
    __shared__ int ws[16];
    if ((t & 31) == 0) ws[t >> 5] = v;
    __syncthreads();
    if (t < 16) {
        int r = ws[t];
        #pragma unroll
        for (int off = 8; off > 0; off >>= 1)
            r += __shfl_down_sync(0x0000ffffu, r, off);
        if (t == 0) part[blockIdx.x] = r;
    }
}

__global__ void __launch_bounds__(256) scan_mid_kernel(int nchunk) {
    __shared__ int wt[8];
    int t = threadIdx.x;
    for (int a = 0; a < 2; a++) {
        int* part = a ? g_partN : g_partP;
        int v = (t < nchunk) ? part[t] : 0;
        int x = v;
        #pragma unroll
        for (int off = 1; off < 32; off <<= 1) {
            int y = __shfl_up_sync(0xffffffffu, x, off);
            if ((t & 31) >= off) x += y;
        }
        if ((t & 31) == 31) wt[t >> 5] = x;
        __syncthreads();
        if (t < 8) {
            int w = wt[t];
            #pragma unroll
            for (int off = 1; off < 8; off <<= 1) {
                int y = __shfl_up_sync(0x000000ffu, w, off);
                if (t >= off) w += y;
            }
            wt[t] = w;
        }
        __syncthreads();
        int incl = x + ((t >> 5) ? wt[(t >> 5) - 1] : 0);
        if (t < nchunk) part[t] = incl - v;
        __syncthreads();
    }
}

__global__ void __launch_bounds__(SCHUNK) scan_final_kernel(int n, int E) {
    const int* deg = blockIdx.y ? g_degN : g_degP;
    const int* part = blockIdx.y ? g_partN : g_partP;
    int* rp = blockIdx.y ? g_rpN : g_rpP;
    int* cur = blockIdx.y ? g_curN : g_curP;
    int t = threadIdx.x;
    int i = blockIdx.x * SCHUNK + t;
    int v = (i < n) ? deg[i] : 0;
    int x = v;
    #pragma unroll
    for (int off = 1; off < 32; off <<= 1) {
        int y = __shfl_up_sync(0xffffffffu, x, off);
        if ((t & 31) >= off) x += y;
    }
    __shared__ int ws[16];
    if ((t & 31) == 31) ws[t >> 5] = x;
    __syncthreads();
    if (t < 16) {
        int w = ws[t];
        #pragma unroll
        for (int off = 1; off < 16; off <<= 1) {
            int y = __shfl_up_sync(0x0000ffffu, w, off);
            if (t >= off) w += y;
        }
        ws[t] = w;
    }
    __syncthreads();
    int incl = x + ((t >> 5) ? ws[(t >> 5) - 1] : 0);
    int excl = incl - v + part[blockIdx.x];
    if (i < n) { rp[i] = excl; cur[i] = excl; }
    if (blockIdx.x == 0 && t == 0) rp[n] = E;
}

__global__ void fill2_kernel(const void* __restrict__ e1, const void* __restrict__ e2,
                             int E) {
    int e = blockIdx.x * blockDim.x + threadIdx.x;
    if (e >= E) return;
    const void* ed = blockIdx.y ? e2 : e1;
    int* cur = blockIdx.y ? g_curN : g_curP;
    int* col = blockIdx.y ? g_colN : g_colP;
    int s, d;
    if (g_is64) {
        s = (int)((const long long*)ed)[e];
        d = (int)((const long long*)ed)[(size_t)E + e];
    } else {
        s = ((const int*)ed)[e];
        d = ((const int*)ed)[(size_t)E + e];
    }
    int slot = atomicAdd(&cur[d], 1);
    col[slot] = s;
}

// ---------------- GEMM: (n x K) @ (K x 64) -> strided 64-col group --------
// half_out: O points to __half array (row stride CH halfs); else float (CH floats)
struct GemmGroup { const float* A; const float* W; const float* bias; void* O; int half_out; };
struct GemmParams { GemmGroup g[6]; int K; int nrows; };

__global__ void __launch_bounds__(256) gemm_kernel(GemmParams p) {
    __shared__ float As[64][128];
    __shared__ float Bs[64][64];
    GemmGroup gg = p.g[blockIdx.y];
    int row0 = blockIdx.x * 128;
    int t = threadIdx.x;
    int tc = t & 15;
    int tr = t >> 4;
    float acc[8][4];
    #pragma unroll
    for (int r = 0; r < 8; r++)
        #pragma unroll
        for (int c = 0; c < 4; c++) acc[r][c] = 0.f;

    for (int kb = 0; kb < p.K; kb += 64) {
        {
            int m = t >> 1;
            int half = t & 1;
            int r = row0 + m;
            const float* ap = gg.A + (size_t)r * CH + kb + half * 32;
            #pragma unroll
            for (int j = 0; j < 8; j++) {
                float4 v = make_float4(0.f, 0.f, 0.f, 0.f);
                if (r < p.nrows) v = *(const float4*)(ap + j * 4);
                int k = half * 32 + j * 4;
                As[k + 0][m] = v.x; As[k + 1][m] = v.y;
                As[k + 2][m] = v.z; As[k + 3][m] = v.w;
            }
        }
        {
            int col = (t & 15) * 4;
            int kr = t >> 4;
            #pragma unroll
            for (int j = 0; j < 4; j++) {
                int k = kr + j * 16;
                *(float4*)&Bs[k][col] = *(const float4*)(gg.W + (size_t)(kb + k) * 64 + col);
            }
        }
        __syncthreads();
        #pragma unroll 16
        for (int kk = 0; kk < 64; kk++) {
            float4 a0 = *(const float4*)&As[kk][tr * 8];
            float4 a1 = *(const float4*)&As[kk][tr * 8 + 4];
            float4 b  = *(const float4*)&Bs[kk][tc * 4];
            float av[8] = {a0.x, a0.y, a0.z, a0.w, a1.x, a1.y, a1.z, a1.w};
            float bv[4] = {b.x, b.y, b.z, b.w};
            #pragma unroll
            for (int r = 0; r < 8; r++)
                #pragma unroll
                for (int c = 0; c < 4; c++)
                    acc[r][c] = fmaf(av[r], bv[c], acc[r][c]);
        }
        __syncthreads();
    }
    float bb[4] = {0.f, 0.f, 0.f, 0.f};
    if (gg.bias) {
        bb[0] = gg.bias[tc * 4 + 0]; bb[1] = gg.bias[tc * 4 + 1];
        bb[2] = gg.bias[tc * 4 + 2]; bb[3] = gg.bias[tc * 4 + 3];
    }
    if (gg.half_out) {
        __half* O = (__half*)gg.O;
        #pragma unroll
        for (int r = 0; r < 8; r++) {
            int row = row0 + tr * 8 + r;
            if (row < p.nrows) {
                __half2 h0 = __floats2half2_rn(acc[r][0] + bb[0], acc[r][1] + bb[1]);
                __half2 h1 = __floats2half2_rn(acc[r][2] + bb[2], acc[r][3] + bb[3]);
                uint2 pk; pk.x = *(unsigned*)&h0; pk.y = *(unsigned*)&h1;
                *(uint2*)(O + (size_t)row * CH + tc * 4) = pk;
            }
        }
    } else {
        float* O = (float*)gg.O;
        #pragma unroll
        for (int r = 0; r < 8; r++) {
            int row = row0 + tr * 8 + r;
            if (row < p.nrows) {
                float4 o = make_float4(acc[r][0] + bb[0], acc[r][1] + bb[1],
                                       acc[r][2] + bb[2], acc[r][3] + bb[3]);
                *(float4*)(O + (size_t)row * CH + tc * 4) = o;
            }
        }
    }
}

// ---------------- layer-0 aggregation: 1 warp per node --------------------
// U is fp16. z[:, :64]=tanh(R[:, :64]+meanpos(U[:, :64])); z[:,64:]=tanh(R[:,64:]+meanneg(U[:,64:]))
__global__ void agg0_kernel(int n, float* __restrict__ Z) {
    int w = (blockIdx.x * blockDim.x + threadIdx.x) >> 5;
    if (w >= n) return;
    int lane = threadIdx.x & 31;
    int c = lane * 2;

    float sx0 = 0.f, sy0 = 0.f, sx1 = 0.f, sy1 = 0.f;
    int b = g_rpP[w], e = g_rpP[w + 1];
    float invp = 1.0f / (float)((e - b) > 0 ? (e - b) : 1);
    int i = b;
    for (; i + 2 <= e; i += 2) {
        int ia = g_colP[i], ib = g_colP[i + 1];
        float2 ga = __half22float2(*(const __half2*)(g_U + (size_t)ia * CH + c));
        float2 gb = __half22float2(*(const __half2*)(g_U + (size_t)ib * CH + c));
        sx0 += ga.x; sy0 += ga.y; sx1 += gb.x; sy1 += gb.y;
    }
    if (i < e) {
        float2 ga = __half22float2(*(const __half2*)(g_U + (size_t)g_colP[i] * CH + c));
        sx0 += ga.x; sy0 += ga.y;
    }
    float sumpx = sx0 + sx1, sumpy = sy0 + sy1;

    float tx0 = 0.f, ty0 = 0.f, tx1 = 0.f, ty1 = 0.f;
    b = g_rpN[w]; e = g_rpN[w + 1];
    float invn = 1.0f / (float)((e - b) > 0 ? (e - b) : 1);
    i = b;
    for (; i + 2 <= e; i += 2) {
        int ia = g_colN[i], ib = g_colN[i + 1];
        float2 ga = __half22float2(*(const __half2*)(g_U + (size_t)ia * CH + 64 + c));
        float2 gb = __half22float2(*(const __half2*)(g_U + (size_t)ib * CH + 64 + c));
        tx0 += ga.x; ty0 += ga.y; tx1 += gb.x; ty1 += gb.y;
    }
    if (i < e) {
        float2 ga = __half22float2(*(const __half2*)(g_U + (size_t)g_colN[i] * CH + 64 + c));
        tx0 += ga.x; ty0 += ga.y;
    }
    float sumnx = tx0 + tx1, sumny = ty0 + ty1;

    float2 r0 = *(const float2*)(g_R + (size_t)w * CH + c);
    float2 r1 = *(const float2*)(g_R + (size_t)w * CH + 64 + c);
    float2 zp, zn;
    zp.x = tanhf(r0.x + invp * sumpx);
    zp.y = tanhf(r0.y + invp * sumpy);
    zn.x = tanhf(r1.x + invn * sumnx);
    zn.y = tanhf(r1.y + invn * sumny);
    *(float2*)(Z + (size_t)w * CH + c) = zp;
    *(float2*)(Z + (size_t)w * CH + 64 + c) = zn;
}

// ---------------- loop-layer aggregation: 1 warp per node, fp16 U/V -------
__global__ void aggl_kernel(int n, float* __restrict__ out) {
    int w = (blockIdx.x * blockDim.x + threadIdx.x) >> 5;
    if (w >= n) return;
    int lane = threadIdx.x & 31;
    int c = lane * 4;

    float4 s0 = make_float4(0.f, 0.f, 0.f, 0.f);
    float4 s1 = make_float4(0.f, 0.f, 0.f, 0.f);
    int b = g_rpP[w], e = g_rpP[w + 1];
    float invp = 1.0f / (float)((e - b) > 0 ? (e - b) : 1);
    int i = b;
    for (; i + 2 <= e; i += 2) {
        int ia = g_colP[i], ib = g_colP[i + 1];
        uint2 pa = *(const uint2*)(g_U + (size_t)ia * CH + c);
        uint2 pb = *(const uint2*)(g_U + (size_t)ib * CH + c);
        float2 a0 = __half22float2(*(__half2*)&pa.x);
        float2 a1 = __half22float2(*(__half2*)&pa.y);
        float2 b0 = __half22float2(*(__half2*)&pb.x);
        float2 b1 = __half22float2(*(__half2*)&pb.y);
        s0.x += a0.x; s0.y += a0.y; s0.z += a1.x; s0.w += a1.y;
        s1.x += b0.x; s1.y += b0.y; s1.z += b1.x; s1.w += b1.y;
    }
    if (i < e) {
        uint2 pa = *(const uint2*)(g_U + (size_t)g_colP[i] * CH + c);
        float2 a0 = __half22float2(*(__half2*)&pa.x);
        float2 a1 = __half22float2(*(__half2*)&pa.y);
        s0.x += a0.x; s0.y += a0.y; s0.z += a1.x; s0.w += a1.y;
    }

    float4 t0 = make_float4(0.f, 0.f, 0.f, 0.f);
    float4 t1 = make_float4(0.f, 0.f, 0.f, 0.f);
    b = g_rpN[w]; e = g_rpN[w + 1];
    float invn = 1.0f / (float)((e - b) > 0 ? (e - b) : 1);
    i = b;
    for (; i + 2 <= e; i += 2) {
        int ia = g_colN[i], ib = g_colN[i + 1];
        uint2 pa = *(const uint2*)(g_V + (size_t)ia * CH + c);
        uint2 pb = *(const uint2*)(g_V + (size_t)ib * CH + c);
        float2 a0 = __half22float2(*(__half2*)&pa.x);
        float2 a1 = __half22float2(*(__half2*)&pa.y);
        float2 b0 = __half22float2(*(__half2*)&pb.x);
        float2 b1 = __half22float2(*(__half2*)&pb.y);
        t0.x += a0.x; t0.y += a0.y; t0.z += a1.x; t0.w += a1.y;
        t1.x += b0.x; t1.y += b0.y; t1.z += b1.x; t1.w += b1.y;
    }
    if (i < e) {
        uint2 pa = *(const uint2*)(g_V + (size_t)g_colN[i] * CH + c);
        float2 a0 = __half22float2(*(__half2*)&pa.x);
        float2 a1 = __half22float2(*(__half2*)&pa.y);
        t0.x += a0.x; t0.y += a0.y; t0.z += a1.x; t0.w += a1.y;
    }

    float4 r = *(const float4*)(g_R + (size_t)w * CH + c);
    float4 o;
    o.x = tanhf(r.x + invp * (s0.x + s1.x) + invn * (t0.x + t1.x));
    o.y = tanhf(r.y + invp * (s0.y + s1.y) + invn * (t0.y + t1.y));
    o.z = tanhf(r.z + invp * (s0.z + s1.z) + invn * (t0.z + t1.z));
    o.w = tanhf(r.w + invp * (s0.w + s1.w) + invn * (t0.w + t1.w));
    *(float4*)(out + (size_t)w * CH + c) = o;
}

// ---------------- host driver --------------------------------------------
extern "C" void kernel_launch(void* const* d_in, const int* in_sizes, int n_in,
                              void* d_out, int out_size) {
    const float* x      = (const float*)d_in[0];
    const void*  pe     = d_in[1];
    const void*  nedge  = d_in[2];
    const float* Wp_l   = (const float*)d_in[3];
    const float* Wp_r   = (const float*)d_in[4];
    const float* bp     = (const float*)d_in[5];
    const float* Wn_l   = (const float*)d_in[6];
    const float* Wn_r   = (const float*)d_in[7];
    const float* bn     = (const float*)d_in[8];
    const float* Wl_pos = (const float*)d_in[9];
    const float* Wr_pos = (const float*)d_in[10];
    const float* b_pos  = (const float*)d_in[11];
    const float* Wl_neg = (const float*)d_in[12];
    const float* Wr_neg = (const float*)d_in[13];
    const float* b_neg  = (const float*)d_in[14];

    int n = in_sizes[0] / CH;
    int E = in_sizes[1] / 2;
    if (n > NN) n = NN;
    if (E > EE) E = EE;

    void *pU, *pV, *pR, *pZ, *pDegP, *pDegN;
    cudaGetSymbolAddress(&pU, g_U);
    cudaGetSymbolAddress(&pV, g_V);
    cudaGetSymbolAddress(&pR, g_R);
    cudaGetSymbolAddress(&pZ, g_Z);
    cudaGetSymbolAddress(&pDegP, g_degP);
    cudaGetSymbolAddress(&pDegN, g_degN);

    cudaMemsetAsync(pDegP, 0, n * sizeof(int));
    cudaMemsetAsync(pDegN, 0, n * sizeof(int));

    detect_kernel<<<1, 1024>>>((const unsigned int*)pe);

    int eg = (E + 255) / 256;
    int nchunk = (n + SCHUNK - 1) / SCHUNK;
    hist2_kernel<<<dim3(eg, 2), 256>>>(pe, nedge, E);
    scan_part_kernel<<<dim3(nchunk, 2), SCHUNK>>>(n);
    scan_mid_kernel<<<1, 256>>>(nchunk);
    scan_final_kernel<<<dim3(nchunk, 2), SCHUNK>>>(n, E);
    fill2_kernel<<<dim3(eg, 2), 256>>>(pe, nedge, E);

    int mg = (n + 127) / 128;
    int wg = (n * 32 + 255) / 256;

    // layer 0
    GemmParams p0;
    p0.K = CH; p0.nrows = n;
    p0.g[0] = GemmGroup{ x, Wp_l, nullptr, (void*)((__half*)pU),        1 };
    p0.g[1] = GemmGroup{ x, Wn_l, nullptr, (void*)(((__half*)pU) + 64), 1 };
    p0.g[2] = GemmGroup{ x, Wp_r, bp,      (void*)((float*)pR),         0 };
    p0.g[3] = GemmGroup{ x, Wn_r, bn,      (void*)(((float*)pR) + 64),  0 };
    p0.g[4] = p0.g[0]; p0.g[5] = p0.g[0];
    gemm_kernel<<<dim3(mg, 4), 256>>>(p0);
    agg0_kernel<<<wg, 256>>>(n, (float*)pZ);

    // loop layers
    for (int l = 0; l < 2; l++) {
        const float* zp = (const float*)pZ;
        const float* zn = (const float*)pZ + 64;
        GemmParams pl;
        pl.K = 64; pl.nrows = n;
        pl.g[0] = GemmGroup{ zp, Wl_pos + l * 8192,        nullptr,        (void*)((__half*)pU),        1 };
        pl.g[1] = GemmGroup{ zn, Wl_neg + l * 8192,        nullptr,        (void*)(((__half*)pU) + 64), 1 };
        pl.g[2] = GemmGroup{ zn, Wl_pos + l * 8192 + 4096, nullptr,        (void*)((__half*)pV),        1 };
        pl.g[3] = GemmGroup{ zp, Wl_neg + l * 8192 + 4096, nullptr,        (void*)(((__half*)pV) + 64), 1 };
        pl.g[4] = GemmGroup{ zp, Wr_pos + l * 4096,        b_pos + l * 64, (void*)((float*)pR),         0 };
        pl.g[5] = GemmGroup{ zn, Wr_neg + l * 4096,        b_neg + l * 64, (void*)(((float*)pR) + 64),  0 };
        gemm_kernel<<<dim3(mg, 6), 256>>>(pl);

        float* outp = (l == 1) ? (float*)d_out : (float*)pZ;
        aggl_kernel<<<wg, 256>>>(n, outp);
    }
}

// round 5
// speedup vs baseline: 1.9860x; 1.4791x over previous
#include <cuda_runtime.h>
#include <cuda_fp16.h>
#include <math.h>

#define NN 100000
#define EE 1200000
#define CH 128
#define SCHUNK 512
#define MAXCHUNK 200

// ---------------- device scratch ----------------
__device__ int g_degP[NN], g_degN[NN], g_curP[NN], g_curN[NN];
__device__ int g_rpP[NN + 1], g_rpN[NN + 1];
__device__ int g_colP[EE], g_colN[EE];
__device__ int g_partP[MAXCHUNK], g_partN[MAXCHUNK];
__device__ __half g_U[(size_t)NN * CH];
__device__ __half g_V[(size_t)NN * CH];
__device__ float g_R[(size_t)NN * CH];
__device__ float g_Z[(size_t)NN * CH];
__device__ int g_is64;

// ---------------- dtype detection ----------------
__global__ void detect_kernel(const unsigned int* __restrict__ p) {
    __shared__ int bad;
    if (threadIdx.x == 0) bad = 0;
    __syncthreads();
    if (p[threadIdx.x * 2 + 1] != 0u) bad = 1;
    __syncthreads();
    if (threadIdx.x == 0) g_is64 = (bad == 0) ? 1 : 0;
}

// ---------------- CSR build ----------------
__global__ void hist2_kernel(const void* __restrict__ e1, const void* __restrict__ e2,
                             int E) {
    int e = blockIdx.x * blockDim.x + threadIdx.x;
    if (e >= E) return;
    const void* ed = blockIdx.y ? e2 : e1;
    int* deg = blockIdx.y ? g_degN : g_degP;
    int d;
    if (g_is64) d = (int)((const long long*)ed)[(size_t)E + e];
    else        d = ((const int*)ed)[(size_t)E + e];
    atomicAdd(&deg[d], 1);
}

__global__ void __launch_bounds__(SCHUNK) scan_part_kernel(int n) {
    const int* deg = blockIdx.y ? g_degN : g_degP;
    int* part = blockIdx.y ? g_partN : g_partP;
    int t = threadIdx.x;
    int i = blockIdx.x * SCHUNK + t;
    int v = (i < n) ? deg[i] : 0;
    #pragma unroll
    for (int off = 16; off > 0; off >>= 1)
        v += __shfl_down_sync(0xffffffffu, v, off);
    __shared__ int ws[16];
    if ((t & 31) == 0) ws[t >> 5] = v;
    __syncthreads();
    if (t < 16) {
        int r = ws[t];
        #pragma unroll
        for (int off = 8; off > 0; off >>= 1)
            r += __shfl_down_sync(0x0000ffffu, r, off);
        if (t == 0) part[blockIdx.x] = r;
    }
}

__global__ void __launch_bounds__(256) scan_mid_kernel(int nchunk) {
    __shared__ int wt[8];
    int t = threadIdx.x;
    for (int a = 0; a < 2; a++) {
        int* part = a ? g_partN : g_partP;
        int v = (t < nchunk) ? part[t] : 0;
        int x = v;
        #pragma unroll
        for (int off = 1; off < 32; off <<= 1) {
            int y = __shfl_up_sync(0xffffffffu, x, off);
            if ((t & 31) >= off) x += y;
        }
        if ((t & 31) == 31) wt[t >> 5] = x;
        __syncthreads();
        if (t < 8) {
            int w = wt[t];
            #pragma unroll
            for (int off = 1; off < 8; off <<= 1) {
                int y = __shfl_up_sync(0x000000ffu, w, off);
                if (t >= off) w += y;
            }
            wt[t] = w;
        }
        __syncthreads();
        int incl = x + ((t >> 5) ? wt[(t >> 5) - 1] : 0);
        if (t < nchunk) part[t] = incl - v;
        __syncthreads();
    }
}

__global__ void __launch_bounds__(SCHUNK) scan_final_kernel(int n, int E) {
    const int* deg = blockIdx.y ? g_degN : g_degP;
    const int* part = blockIdx.y ? g_partN : g_partP;
    int* rp = blockIdx.y ? g_rpN : g_rpP;
    int* cur = blockIdx.y ? g_curN : g_curP;
    int t = threadIdx.x;
    int i = blockIdx.x * SCHUNK + t;
    int v = (i < n) ? deg[i] : 0;
    int x = v;
    #pragma unroll
    for (int off = 1; off < 32; off <<= 1) {
        int y = __shfl_up_sync(0xffffffffu, x, off);
        if ((t & 31) >= off) x += y;
    }
    __shared__ int ws[16];
    if ((t & 31) == 31) ws[t >> 5] = x;
    __syncthreads();
    if (t < 16) {
        int w = ws[t];
        #pragma unroll
        for (int off = 1; off < 16; off <<= 1) {
            int y = __shfl_up_sync(0x0000ffffu, w, off);
            if (t >= off) w += y;
        }
        ws[t] = w;
    }
    __syncthreads();
    int incl = x + ((t >> 5) ? ws[(t >> 5) - 1] : 0);
    int excl = incl - v + part[blockIdx.x];
    if (i < n) { rp[i] = excl; cur[i] = excl; }
    if (blockIdx.x == 0 && t == 0) rp[n] = E;
}

__global__ void fill2_kernel(const void* __restrict__ e1, const void* __restrict__ e2,
                             int E) {
    int e = blockIdx.x * blockDim.x + threadIdx.x;
    if (e >= E) return;
    const void* ed = blockIdx.y ? e2 : e1;
    int* cur = blockIdx.y ? g_curN : g_curP;
    int* col = blockIdx.y ? g_colN : g_colP;
    int s, d;
    if (g_is64) {
        s = (int)((const long long*)ed)[e];
        d = (int)((const long long*)ed)[(size_t)E + e];
    } else {
        s = ((const int*)ed)[e];
        d = ((const int*)ed)[(size_t)E + e];
    }
    int slot = atomicAdd(&cur[d], 1);
    col[slot] = s;
}

// ---------------- tensor-core GEMM: (n x K) @ (K x 64) --------------------
// fp16 inputs (converted on smem staging), fp32 accumulate via HMMA 16x8x16.
struct GemmGroup { const float* A; const float* W; const float* bias; void* O; int half_out; };
struct GemmParams { GemmGroup g[6]; int K; int nrows; };

#define APAD 72   // half-elements per As/Bs row (64 + 8 pad -> conflict-free frags)

__device__ __forceinline__ void mma16816(float* c, const unsigned* a, const unsigned* b) {
    asm volatile(
        "mma.sync.aligned.m16n8k16.row.col.f32.f16.f16.f32 "
        "{%0,%1,%2,%3}, {%4,%5,%6,%7}, {%8,%9}, {%0,%1,%2,%3};"
        : "+f"(c[0]), "+f"(c[1]), "+f"(c[2]), "+f"(c[3])
        : "r"(a[0]), "r"(a[1]), "r"(a[2]), "r"(a[3]), "r"(b[0]), "r"(b[1]));
}

__global__ void __launch_bounds__(256) gemm_kernel(GemmParams p) {
    __shared__ __half As[128][APAD];   // [m][k]
    __shared__ __half Bs[64][APAD];    // [n][k]  (transposed on fill)
    GemmGroup gg = p.g[blockIdx.y];
    int row0 = blockIdx.x * 128;
    int t = threadIdx.x;
    int lane = t & 31;
    int warp = t >> 5;
    int g = lane >> 2;       // 0..7
    int tg = lane & 3;       // 0..3
    int wr = warp >> 1;      // warp row 0..3  -> rows wr*32..+31
    int wc = warp & 1;       // warp col 0..1  -> cols wc*32..+31

    float acc[2][4][4];
    #pragma unroll
    for (int m = 0; m < 2; m++)
        #pragma unroll
        for (int nt = 0; nt < 4; nt++)
            #pragma unroll
            for (int i = 0; i < 4; i++) acc[m][nt][i] = 0.f;

    for (int kb = 0; kb < p.K; kb += 64) {
        // stage A: 128 rows x 64 k, fp32 -> fp16
        #pragma unroll
        for (int j = 0; j < 8; j++) {
            int idx = j * 256 + t;
            int r = idx >> 4;
            int cg = (idx & 15) * 4;
            float4 v = make_float4(0.f, 0.f, 0.f, 0.f);
            if (row0 + r < p.nrows)
                v = *(const float4*)(gg.A + (size_t)(row0 + r) * CH + kb + cg);
            __half2 h0 = __floats2half2_rn(v.x, v.y);
            __half2 h1 = __floats2half2_rn(v.z, v.w);
            uint2 pk; pk.x = *(unsigned*)&h0; pk.y = *(unsigned*)&h1;
            *(uint2*)&As[r][cg] = pk;
        }
        // stage B transposed: W is [k][64] row-major -> Bs[n][k]
        #pragma unroll
        for (int j = 0; j < 4; j++) {
            int idx = j * 256 + t;
            int k = idx >> 4;
            int ng = (idx & 15) * 4;
            float4 v = *(const float4*)(gg.W + (size_t)(kb + k) * 64 + ng);
            Bs[ng + 0][k] = __float2half_rn(v.x);
            Bs[ng + 1][k] = __float2half_rn(v.y);
            Bs[ng + 2][k] = __float2half_rn(v.z);
            Bs[ng + 3][k] = __float2half_rn(v.w);
        }
        __syncthreads();

        #pragma unroll
        for (int kk = 0; kk < 64; kk += 16) {
            unsigned a[2][4];
            #pragma unroll
            for (int m = 0; m < 2; m++) {
                int ar = wr * 32 + m * 16;
                a[m][0] = *(const unsigned*)&As[ar + g][kk + tg * 2];
                a[m][1] = *(const unsigned*)&As[ar + g + 8][kk + tg * 2];
                a[m][2] = *(const unsigned*)&As[ar + g][kk + tg * 2 + 8];
                a[m][3] = *(const unsigned*)&As[ar + g + 8][kk + tg * 2 + 8];
            }
            unsigned b[4][2];
            #pragma unroll
            for (int nt = 0; nt < 4; nt++) {
                int br = wc * 32 + nt * 8 + g;
                b[nt][0] = *(const unsigned*)&Bs[br][kk + tg * 2];
                b[nt][1] = *(const unsigned*)&Bs[br][kk + tg * 2 + 8];
            }
            #pragma unroll
            for (int m = 0; m < 2; m++)
                #pragma unroll
                for (int nt = 0; nt < 4; nt++)
                    mma16816(acc[m][nt], a[m], b[nt]);
        }
        __syncthreads();
    }

    // epilogue: bias + store (acc c0,c1 -> row g; c2,c3 -> row g+8; cols tg*2,+1)
    float bb0[4], bb1[4];
    #pragma unroll
    for (int nt = 0; nt < 4; nt++) {
        int col = wc * 32 + nt * 8 + tg * 2;
        bb0[nt] = gg.bias ? gg.bias[col] : 0.f;
        bb1[nt] = gg.bias ? gg.bias[col + 1] : 0.f;
    }
    #pragma unroll
    for (int m = 0; m < 2; m++) {
        int r1 = row0 + wr * 32 + m * 16 + g;
        int r2 = r1 + 8;
        #pragma unroll
        for (int nt = 0; nt < 4; nt++) {
            int col = wc * 32 + nt * 8 + tg * 2;
            if (gg.half_out) {
                __half* O = (__half*)gg.O;
                if (r1 < p.nrows) {
                    __half2 h = __floats2half2_rn(acc[m][nt][0] + bb0[nt], acc[m][nt][1] + bb1[nt]);
                    *(__half2*)(O + (size_t)r1 * CH + col) = h;
                }
                if (r2 < p.nrows) {
                    __half2 h = __floats2half2_rn(acc[m][nt][2] + bb0[nt], acc[m][nt][3] + bb1[nt]);
                    *(__half2*)(O + (size_t)r2 * CH + col) = h;
                }
            } else {
                float* O = (float*)gg.O;
                if (r1 < p.nrows) {
                    float2 f = make_float2(acc[m][nt][0] + bb0[nt], acc[m][nt][1] + bb1[nt]);
                    *(float2*)(O + (size_t)r1 * CH + col) = f;
                }
                if (r2 < p.nrows) {
                    float2 f = make_float2(acc[m][nt][2] + bb0[nt], acc[m][nt][3] + bb1[nt]);
                    *(float2*)(O + (size_t)r2 * CH + col) = f;
                }
            }
        }
    }
}

// ---------------- layer-0 aggregation: 1 warp per node --------------------
__global__ void agg0_kernel(int n, float* __restrict__ Z) {
    int w = (blockIdx.x * blockDim.x + threadIdx.x) >> 5;
    if (w >= n) return;
    int lane = threadIdx.x & 31;
    int c = lane * 2;

    float sx0 = 0.f, sy0 = 0.f, sx1 = 0.f, sy1 = 0.f;
    int b = g_rpP[w], e = g_rpP[w + 1];
    float invp = 1.0f / (float)((e - b) > 0 ? (e - b) : 1);
    int i = b;
    for (; i + 2 <= e; i += 2) {
        int ia = g_colP[i], ib = g_colP[i + 1];
        float2 ga = __half22float2(*(const __half2*)(g_U + (size_t)ia * CH + c));
        float2 gb = __half22float2(*(const __half2*)(g_U + (size_t)ib * CH + c));
        sx0 += ga.x; sy0 += ga.y; sx1 += gb.x; sy1 += gb.y;
    }
    if (i < e) {
        float2 ga = __half22float2(*(const __half2*)(g_U + (size_t)g_colP[i] * CH + c));
        sx0 += ga.x; sy0 += ga.y;
    }
    float sumpx = sx0 + sx1, sumpy = sy0 + sy1;

    float tx0 = 0.f, ty0 = 0.f, tx1 = 0.f, ty1 = 0.f;
    b = g_rpN[w]; e = g_rpN[w + 1];
    float invn = 1.0f / (float)((e - b) > 0 ? (e - b) : 1);
    i = b;
    for (; i + 2 <= e; i += 2) {
        int ia = g_colN[i], ib = g_colN[i + 1];
        float2 ga = __half22float2(*(const __half2*)(g_U + (size_t)ia * CH + 64 + c));
        float2 gb = __half22float2(*(const __half2*)(g_U + (size_t)ib * CH + 64 + c));
        tx0 += ga.x; ty0 += ga.y; tx1 += gb.x; ty1 += gb.y;
    }
    if (i < e) {
        float2 ga = __half22float2(*(const __half2*)(g_U + (size_t)g_colN[i] * CH + 64 + c));
        tx0 += ga.x; ty0 += ga.y;
    }
    float sumnx = tx0 + tx1, sumny = ty0 + ty1;

    float2 r0 = *(const float2*)(g_R + (size_t)w * CH + c);
    float2 r1 = *(const float2*)(g_R + (size_t)w * CH + 64 + c);
    float2 zp, zn;
    zp.x = tanhf(r0.x + invp * sumpx);
    zp.y = tanhf(r0.y + invp * sumpy);
    zn.x = tanhf(r1.x + invn * sumnx);
    zn.y = tanhf(r1.y + invn * sumny);
    *(float2*)(Z + (size_t)w * CH + c) = zp;
    *(float2*)(Z + (size_t)w * CH + 64 + c) = zn;
}

// ---------------- loop-layer aggregation: 1 warp per node, fp16 U/V -------
__global__ void aggl_kernel(int n, float* __restrict__ out) {
    int w = (blockIdx.x * blockDim.x + threadIdx.x) >> 5;
    if (w >= n) return;
    int lane = threadIdx.x & 31;
    int c = lane * 4;

    float4 s0 = make_float4(0.f, 0.f, 0.f, 0.f);
    float4 s1 = make_float4(0.f, 0.f, 0.f, 0.f);
    int b = g_rpP[w], e = g_rpP[w + 1];
    float invp = 1.0f / (float)((e - b) > 0 ? (e - b) : 1);
    int i = b;
    for (; i + 2 <= e; i += 2) {
        int ia = g_colP[i], ib = g_colP[i + 1];
        uint2 pa = *(const uint2*)(g_U + (size_t)ia * CH + c);
        uint2 pb = *(const uint2*)(g_U + (size_t)ib * CH + c);
        float2 a0 = __half22float2(*(__half2*)&pa.x);
        float2 a1 = __half22float2(*(__half2*)&pa.y);
        float2 b0 = __half22float2(*(__half2*)&pb.x);
        float2 b1 = __half22float2(*(__half2*)&pb.y);
        s0.x += a0.x; s0.y += a0.y; s0.z += a1.x; s0.w += a1.y;
        s1.x += b0.x; s1.y += b0.y; s1.z += b1.x; s1.w += b1.y;
    }
    if (i < e) {
        uint2 pa = *(const uint2*)(g_U + (size_t)g_colP[i] * CH + c);
        float2 a0 = __half22float2(*(__half2*)&pa.x);
        float2 a1 = __half22float2(*(__half2*)&pa.y);
        s0.x += a0.x; s0.y += a0.y; s0.z += a1.x; s0.w += a1.y;
    }

    float4 t0 = make_float4(0.f, 0.f, 0.f, 0.f);
    float4 t1 = make_float4(0.f, 0.f, 0.f, 0.f);
    b = g_rpN[w]; e = g_rpN[w + 1];
    float invn = 1.0f / (float)((e - b) > 0 ? (e - b) : 1);
    i = b;
    for (; i + 2 <= e; i += 2) {
        int ia = g_colN[i], ib = g_colN[i + 1];
        uint2 pa = *(const uint2*)(g_V + (size_t)ia * CH + c);
        uint2 pb = *(const uint2*)(g_V + (size_t)ib * CH + c);
        float2 a0 = __half22float2(*(__half2*)&pa.x);
        float2 a1 = __half22float2(*(__half2*)&pa.y);
        float2 b0 = __half22float2(*(__half2*)&pb.x);
        float2 b1 = __half22float2(*(__half2*)&pb.y);
        t0.x += a0.x; t0.y += a0.y; t0.z += a1.x; t0.w += a1.y;
        t1.x += b0.x; t1.y += b0.y; t1.z += b1.x; t1.w += b1.y;
    }
    if (i < e) {
        uint2 pa = *(const uint2*)(g_V + (size_t)g_colN[i] * CH + c);
        float2 a0 = __half22float2(*(__half2*)&pa.x);
        float2 a1 = __half22float2(*(__half2*)&pa.y);
        t0.x += a0.x; t0.y += a0.y; t0.z += a1.x; t0.w += a1.y;
    }

    float4 r = *(const float4*)(g_R + (size_t)w * CH + c);
    float4 o;
    o.x = tanhf(r.x + invp * (s0.x + s1.x) + invn * (t0.x + t1.x));
    o.y = tanhf(r.y + invp * (s0.y + s1.y) + invn * (t0.y + t1.y));
    o.z = tanhf(r.z + invp * (s0.z + s1.z) + invn * (t0.z + t1.z));
    o.w = tanhf(r.w + invp * (s0.w + s1.w) + invn * (t0.w + t1.w));
    *(float4*)(out + (size_t)w * CH + c) = o;
}

// ---------------- host driver --------------------------------------------
extern "C" void kernel_launch(void* const* d_in, const int* in_sizes, int n_in,
                              void* d_out, int out_size) {
    const float* x      = (const float*)d_in[0];
    const void*  pe     = d_in[1];
    const void*  nedge  = d_in[2];
    const float* Wp_l   = (const float*)d_in[3];
    const float* Wp_r   = (const float*)d_in[4];
    const float* bp     = (const float*)d_in[5];
    const float* Wn_l   = (const float*)d_in[6];
    const float* Wn_r   = (const float*)d_in[7];
    const float* bn     = (const float*)d_in[8];
    const float* Wl_pos = (const float*)d_in[9];
    const float* Wr_pos = (const float*)d_in[10];
    const float* b_pos  = (const float*)d_in[11];
    const float* Wl_neg = (const float*)d_in[12];
    const float* Wr_neg = (const float*)d_in[13];
    const float* b_neg  = (const float*)d_in[14];

    int n = in_sizes[0] / CH;
    int E = in_sizes[1] / 2;
    if (n > NN) n = NN;
    if (E > EE) E = EE;

    void *pU, *pV, *pR, *pZ, *pDegP, *pDegN;
    cudaGetSymbolAddress(&pU, g_U);
    cudaGetSymbolAddress(&pV, g_V);
    cudaGetSymbolAddress(&pR, g_R);
    cudaGetSymbolAddress(&pZ, g_Z);
    cudaGetSymbolAddress(&pDegP, g_degP);
    cudaGetSymbolAddress(&pDegN, g_degN);

    cudaMemsetAsync(pDegP, 0, n * sizeof(int));
    cudaMemsetAsync(pDegN, 0, n * sizeof(int));

    detect_kernel<<<1, 1024>>>((const unsigned int*)pe);

    int eg = (E + 255) / 256;
    int nchunk = (n + SCHUNK - 1) / SCHUNK;
    hist2_kernel<<<dim3(eg, 2), 256>>>(pe, nedge, E);
    scan_part_kernel<<<dim3(nchunk, 2), SCHUNK>>>(n);
    scan_mid_kernel<<<1, 256>>>(nchunk);
    scan_final_kernel<<<dim3(nchunk, 2), SCHUNK>>>(n, E);
    fill2_kernel<<<dim3(eg, 2), 256>>>(pe, nedge, E);

    int mg = (n + 127) / 128;
    int wg = (n * 32 + 255) / 256;

    // layer 0
    GemmParams p0;
    p0.K = CH; p0.nrows = n;
    p0.g[0] = GemmGroup{ x, Wp_l, nullptr, (void*)((__half*)pU),        1 };
    p0.g[1] = GemmGroup{ x, Wn_l, nullptr, (void*)(((__half*)pU) + 64), 1 };
    p0.g[2] = GemmGroup{ x, Wp_r, bp,      (void*)((float*)pR),         0 };
    p0.g[3] = GemmGroup{ x, Wn_r, bn,      (void*)(((float*)pR) + 64),  0 };
    p0.g[4] = p0.g[0]; p0.g[5] = p0.g[0];
    gemm_kernel<<<dim3(mg, 4), 256>>>(p0);
    agg0_kernel<<<wg, 256>>>(n, (float*)pZ);

    // loop layers
    for (int l = 0; l < 2; l++) {
        const float* zp = (const float*)pZ;
        const float* zn = (const float*)pZ + 64;
        GemmParams pl;
        pl.K = 64; pl.nrows = n;
        pl.g[0] = GemmGroup{ zp, Wl_pos + l * 8192,        nullptr,        (void*)((__half*)pU),        1 };
        pl.g[1] = GemmGroup{ zn, Wl_neg + l * 8192,        nullptr,        (void*)(((__half*)pU) + 64), 1 };
        pl.g[2] = GemmGroup{ zn, Wl_pos + l * 8192 + 4096, nullptr,        (void*)((__half*)pV),        1 };
        pl.g[3] = GemmGroup{ zp, Wl_neg + l * 8192 + 4096, nullptr,        (void*)(((__half*)pV) + 64), 1 };
        pl.g[4] = GemmGroup{ zp, Wr_pos + l * 4096,        b_pos + l * 64, (void*)((float*)pR),         0 };
        pl.g[5] = GemmGroup{ zn, Wr_neg + l * 4096,        b_neg + l * 64, (void*)(((float*)pR) + 64),  0 };
        gemm_kernel<<<dim3(mg, 6), 256>>>(pl);

        float* outp = (l == 1) ? (float*)d_out : (float*)pZ;
        aggl_kernel<<<wg, 256>>>(n, outp);
    }
}